// round 7
// baseline (speedup 1.0000x reference)
#include <cuda_runtime.h>
#include <cuda_bf16.h>
#include <stdint.h>

#define NN  100000
#define PP  3200000
#define IN_F  19
#define OUT_F 64
#define CAP   128
#define EPS   1e-5f
#define SLOPE 0.01f
#define FULL 0xffffffffu

#define FILL_BLOCKS 3125                 // PP / 4 / 256
#define NODE_WARP_BLOCKS 12500           // NN*32 / 256
#define MT 128                           // nodes per fused gather+MLP tile
#define GM_BLOCKS ((NN + MT - 1) / MT)   // 782
#define SO_STRIDE 132                    // padded row stride (floats)
#define FINAL_BLOCKS ((NN * OUT_F / 4 + 255) / 256)   // 6250

// ---------------- device scratch (zero-initialized at module load; restored every call) ----------------
__device__ __align__(256) float g_xw[NN * OUT_F];     // x @ W_conv
__device__ __align__(256) float g_edge[NN * OUT_F];   // per-hyperedge features
__device__ __align__(256) float g_h[NN * OUT_F];      // pre-BN MLP output
__device__ __align__(256) float g_res[NN * OUT_F];    // residual x @ W_res + b_res
__device__ int   g_Bcnt[NN];             // hyperedge sizes   (re-zeroed in k_final)
__device__ int   g_Dcnt[NN];             // node degrees      (re-zeroed in k_final)
__device__ int   g_Elist[NN * CAP];      // node ids bucketed by edge
__device__ int   g_Nlist[NN * CAP];      // edge ids bucketed by node
__device__ __align__(16) float g_stats[4 * OUT_F];  // sum | sumsq | scale | shift (sums re-zeroed)
__device__ int   g_arrive;               // arrival counter (reset each call)

// ---------------- fused: bucket fill (blocks [0,FILL_BLOCKS)) + xw & residual GEMMs (rest) ----------------
__global__ void k_fill_xw(const void* __restrict__ idx,
                          const float* __restrict__ x, const float* __restrict__ Wc,
                          const float* __restrict__ Wr, const float* __restrict__ br) {
    __shared__ float sWc[IN_F * OUT_F];
    __shared__ float sWr[IN_F * OUT_F];
    __shared__ int s64;

    if (blockIdx.x < FILL_BLOCKS) {
        // per-block index dtype probe: int64 values < 2^32 => odd 32-bit words all zero
        if (threadIdx.x == 0) {
            const int* w = (const int*)idx;
            int is64 = 1;
            for (int j = 1; j < 64; j += 2)
                if (w[j] != 0) { is64 = 0; break; }
            s64 = is64;
        }
        __syncthreads();

        long long t4 = ((long long)blockIdx.x * blockDim.x + threadIdx.x);
        int n4[4], e4[4];
        if (s64) {
            const longlong2* b = (const longlong2*)idx;
            longlong2 a0 = b[t4 * 2], a1 = b[t4 * 2 + 1];
            longlong2 c0 = b[(PP / 2) + t4 * 2], c1 = b[(PP / 2) + t4 * 2 + 1];
            n4[0] = (int)a0.x; n4[1] = (int)a0.y; n4[2] = (int)a1.x; n4[3] = (int)a1.y;
            e4[0] = (int)c0.x; e4[1] = (int)c0.y; e4[2] = (int)c1.x; e4[3] = (int)c1.y;
        } else {
            const int4* b = (const int4*)idx;
            int4 a = b[t4];
            int4 c = b[(PP / 4) + t4];
            n4[0] = a.x; n4[1] = a.y; n4[2] = a.z; n4[3] = a.w;
            e4[0] = c.x; e4[1] = c.y; e4[2] = c.z; e4[3] = c.w;
        }
#pragma unroll
        for (int q = 0; q < 4; q++) {
            int n = n4[q], e = e4[q];
            if ((unsigned)n >= NN || (unsigned)e >= NN) continue;
            int pe = atomicAdd(&g_Bcnt[e], 1);
            if (pe < CAP) g_Elist[e * CAP + pe] = n;
            int pn = atomicAdd(&g_Dcnt[n], 1);
            if (pn < CAP) g_Nlist[n * CAP + pn] = e;
        }
    } else {
        // ---- xw = x @ W_conv and res = x @ W_res + b_res, one warp per node ----
        for (int i = threadIdx.x; i < IN_F * OUT_F; i += blockDim.x) {
            sWc[i] = Wc[i];
            sWr[i] = Wr[i];
        }
        __syncthreads();

        int warp = (int)(((long long)(blockIdx.x - FILL_BLOCKS) * blockDim.x + threadIdx.x) >> 5);
        int lane = threadIdx.x & 31;
        if (warp >= NN) return;

        float xv = (lane < IN_F) ? x[(int64_t)warp * IN_F + lane] : 0.f;
        float a0 = 0.f, a1 = 0.f;
        float r0 = br[lane], r1 = br[lane + 32];
#pragma unroll
        for (int k = 0; k < IN_F; k++) {
            float xk = __shfl_sync(FULL, xv, k);
            a0 = fmaf(xk, sWc[k * OUT_F + lane],      a0);
            a1 = fmaf(xk, sWc[k * OUT_F + lane + 32], a1);
            r0 = fmaf(xk, sWr[k * OUT_F + lane],      r0);
            r1 = fmaf(xk, sWr[k * OUT_F + lane + 32], r1);
        }
        g_xw[warp * OUT_F + lane]       = a0;
        g_xw[warp * OUT_F + lane + 32]  = a1;
        g_res[warp * OUT_F + lane]      = r0;
        g_res[warp * OUT_F + lane + 32] = r1;
    }
}

// ---------------- pass 1: gather node rows -> edge rows (B^-1 fused) ----------------
__global__ void k_gather_edge() {
    int warp = (blockIdx.x * blockDim.x + threadIdx.x) >> 5;
    int lane = threadIdx.x & 31;
    if (warp >= NN) return;

    int cnt = min(g_Bcnt[warp], CAP);
    const int* lst = &g_Elist[warp * CAP];
    int hw = lane >> 4, sl = lane & 15;

    float4 acc = make_float4(0.f, 0.f, 0.f, 0.f);
    for (int jb = 0; jb < cnt; jb += 32) {
        int m = (jb + lane < cnt) ? lst[jb + lane] : 0;
        int lim = min(32, cnt - jb);
        int even = lim & ~1;
#pragma unroll 4
        for (int k = 0; k < even; k += 2) {
            int n = __shfl_sync(FULL, m, k + hw);
            float4 v = *reinterpret_cast<const float4*>(&g_xw[n * OUT_F + sl * 4]);
            acc.x += v.x; acc.y += v.y; acc.z += v.z; acc.w += v.w;
        }
        if (lim & 1) {
            int n = __shfl_sync(FULL, m, even);
            if (hw == 0) {
                float4 v = *reinterpret_cast<const float4*>(&g_xw[n * OUT_F + sl * 4]);
                acc.x += v.x; acc.y += v.y; acc.z += v.z; acc.w += v.w;
            }
        }
    }
    acc.x += __shfl_xor_sync(FULL, acc.x, 16);
    acc.y += __shfl_xor_sync(FULL, acc.y, 16);
    acc.z += __shfl_xor_sync(FULL, acc.z, 16);
    acc.w += __shfl_xor_sync(FULL, acc.w, 16);

    float s = (cnt > 0) ? (1.f / (float)cnt) : 0.f;
    acc.x *= s; acc.y *= s; acc.z *= s; acc.w *= s;
    if (hw == 0)
        *reinterpret_cast<float4*>(&g_edge[warp * OUT_F + sl * 4]) = acc;
}

// ---------------- fused pass 2 + MLP: gather edge rows -> conv out (into smem, transposed)
//                  -> tiled GEMM h = o@Wm + bm -> BN partials (last block finalizes) ----------------
__global__ __launch_bounds__(256) void k_gather_mlp(
        const float* __restrict__ Wm, const float* __restrict__ bm,
        const float* __restrict__ bc,
        const float* __restrict__ gamma, const float* __restrict__ beta) {
    __shared__ float sO[OUT_F * SO_STRIDE];   // [k][node], padded  (33.8 KB)
    __shared__ float sW[OUT_F * OUT_F];       // [k][f]             (16 KB)
    __shared__ float sred[2 * OUT_F];
    __shared__ int sLast;

    int tid = threadIdx.x;
    int wid = tid >> 5, lane = tid & 31;
    int hw = lane >> 4, sl = lane & 15;

    for (int i = tid; i < OUT_F * OUT_F; i += 256) sW[i] = Wm[i];
    if (tid < 2 * OUT_F) sred[tid] = 0.f;

    int base = blockIdx.x * MT;
    float4 bc4 = *reinterpret_cast<const float4*>(&bc[sl * 4]);

    // ---- gather phase: warp w handles nodes base + w*16 .. +15 ----
    for (int i = 0; i < 16; i++) {
        int col = wid * 16 + i;
        int node = base + col;
        float4 acc = make_float4(0.f, 0.f, 0.f, 0.f);
        int cnt = 0;
        if (node < NN) {
            cnt = min(g_Dcnt[node], CAP);
            const int* lst = &g_Nlist[node * CAP];
            for (int jb = 0; jb < cnt; jb += 32) {
                int m = (jb + lane < cnt) ? lst[jb + lane] : 0;
                int lim = min(32, cnt - jb);
                int even = lim & ~1;
#pragma unroll 4
                for (int k = 0; k < even; k += 2) {
                    int e = __shfl_sync(FULL, m, k + hw);
                    float4 v = *reinterpret_cast<const float4*>(&g_edge[e * OUT_F + sl * 4]);
                    acc.x += v.x; acc.y += v.y; acc.z += v.z; acc.w += v.w;
                }
                if (lim & 1) {
                    int e = __shfl_sync(FULL, m, even);
                    if (hw == 0) {
                        float4 v = *reinterpret_cast<const float4*>(&g_edge[e * OUT_F + sl * 4]);
                        acc.x += v.x; acc.y += v.y; acc.z += v.z; acc.w += v.w;
                    }
                }
            }
        }
        acc.x += __shfl_xor_sync(FULL, acc.x, 16);
        acc.y += __shfl_xor_sync(FULL, acc.y, 16);
        acc.z += __shfl_xor_sync(FULL, acc.z, 16);
        acc.w += __shfl_xor_sync(FULL, acc.w, 16);

        float dinv = (cnt > 0) ? (1.f / (float)cnt) : 0.f;
        if (hw == 0) {
            // o = acc * D^-1 + b_conv ; write transposed into sO[k][col]
            sO[(sl * 4 + 0) * SO_STRIDE + col] = acc.x * dinv + bc4.x;
            sO[(sl * 4 + 1) * SO_STRIDE + col] = acc.y * dinv + bc4.y;
            sO[(sl * 4 + 2) * SO_STRIDE + col] = acc.z * dinv + bc4.z;
            sO[(sl * 4 + 3) * SO_STRIDE + col] = acc.w * dinv + bc4.w;
        }
    }
    __syncthreads();

    // ---- GEMM phase: thread (ngrp=lane, fgrp=wid) computes 4 nodes x 8 feats ----
    int ngrp = lane, fgrp = wid;
    float bmv[8];
#pragma unroll
    for (int j = 0; j < 8; j++) bmv[j] = bm[fgrp * 8 + j];

    float acc[4][8];
#pragma unroll
    for (int i = 0; i < 4; i++)
#pragma unroll
        for (int j = 0; j < 8; j++) acc[i][j] = bmv[j];

#pragma unroll 8
    for (int k = 0; k < OUT_F; k++) {
        float4 o4 = *reinterpret_cast<const float4*>(&sO[k * SO_STRIDE + ngrp * 4]);
        float4 w0 = *reinterpret_cast<const float4*>(&sW[k * OUT_F + fgrp * 8]);
        float4 w1 = *reinterpret_cast<const float4*>(&sW[k * OUT_F + fgrp * 8 + 4]);
        float o[4] = {o4.x, o4.y, o4.z, o4.w};
        float w[8] = {w0.x, w0.y, w0.z, w0.w, w1.x, w1.y, w1.z, w1.w};
#pragma unroll
        for (int i = 0; i < 4; i++)
#pragma unroll
            for (int j = 0; j < 8; j++)
                acc[i][j] = fmaf(o[i], w[j], acc[i][j]);
    }

    // ---- store h + BN partials (valid nodes only) ----
    float s[8], q[8];
#pragma unroll
    for (int j = 0; j < 8; j++) { s[j] = 0.f; q[j] = 0.f; }
#pragma unroll
    for (int i = 0; i < 4; i++) {
        int node = base + ngrp * 4 + i;
        if (node < NN) {
            float4 h0 = make_float4(acc[i][0], acc[i][1], acc[i][2], acc[i][3]);
            float4 h1 = make_float4(acc[i][4], acc[i][5], acc[i][6], acc[i][7]);
            *reinterpret_cast<float4*>(&g_h[node * OUT_F + fgrp * 8])     = h0;
            *reinterpret_cast<float4*>(&g_h[node * OUT_F + fgrp * 8 + 4]) = h1;
#pragma unroll
            for (int j = 0; j < 8; j++) {
                s[j] += acc[i][j];
                q[j] += acc[i][j] * acc[i][j];
            }
        }
    }
#pragma unroll
    for (int off = 16; off > 0; off >>= 1) {
#pragma unroll
        for (int j = 0; j < 8; j++) {
            s[j] += __shfl_xor_sync(FULL, s[j], off);
            q[j] += __shfl_xor_sync(FULL, q[j], off);
        }
    }
    if (ngrp == 0) {
#pragma unroll
        for (int j = 0; j < 8; j++) {
            atomicAdd(&sred[fgrp * 8 + j],         s[j]);
            atomicAdd(&sred[OUT_F + fgrp * 8 + j], q[j]);
        }
    }
    __syncthreads();
    if (tid < 2 * OUT_F) atomicAdd(&g_stats[tid], sred[tid]);

    // ---- last block finalizes BN scale/shift and resets sums ----
    __threadfence();
    if (tid == 0) {
        int prev = atomicAdd(&g_arrive, 1);
        sLast = (prev == gridDim.x - 1);
    }
    __syncthreads();
    if (sLast) {
        if (tid < OUT_F) {
            int f = tid;
            float mean = g_stats[f] / (float)NN;
            float var  = g_stats[OUT_F + f] / (float)NN - mean * mean;
            float inv  = rsqrtf(var + EPS);
            float sc   = gamma[f] * inv;
            g_stats[2 * OUT_F + f] = sc;
            g_stats[3 * OUT_F + f] = beta[f] - sc * mean;
            g_stats[f] = 0.f;
            g_stats[OUT_F + f] = 0.f;
        }
        if (tid == 0) g_arrive = 0;
    }
}

// ---------------- final: BN apply + LeakyReLU + residual + LeakyReLU (pure elementwise) ----------------
__global__ void k_final(float* __restrict__ out) {
    int i = blockIdx.x * blockDim.x + threadIdx.x;
    if (i < NN) { g_Bcnt[i] = 0; g_Dcnt[i] = 0; }   // restore zeros for next call
    if (i >= NN * (OUT_F / 4)) return;

    int f4 = i & 15;           // feature group (x4)
    float4 h  = reinterpret_cast<const float4*>(g_h)[i];
    float4 r  = reinterpret_cast<const float4*>(g_res)[i];
    float4 sc = *reinterpret_cast<const float4*>(&g_stats[2 * OUT_F + f4 * 4]);
    float4 sh = *reinterpret_cast<const float4*>(&g_stats[3 * OUT_F + f4 * 4]);

    float y[4];
    y[0] = h.x * sc.x + sh.x; y[1] = h.y * sc.y + sh.y;
    y[2] = h.z * sc.z + sh.z; y[3] = h.w * sc.w + sh.w;
    float rr[4] = {r.x, r.y, r.z, r.w};
#pragma unroll
    for (int j = 0; j < 4; j++) {
        float v = y[j];
        v = (v >= 0.f) ? v : SLOPE * v;
        v += rr[j];
        y[j] = (v >= 0.f) ? v : SLOPE * v;
    }
    reinterpret_cast<float4*>(out)[i] = make_float4(y[0], y[1], y[2], y[3]);
}

// ---------------- launcher ----------------
extern "C" void kernel_launch(void* const* d_in, const int* in_sizes, int n_in,
                              void* d_out, int out_size) {
    const float* x     = (const float*)d_in[0];
    const void*  hidx  = d_in[1];
    const float* Wc    = (const float*)d_in[2];
    const float* bc    = (const float*)d_in[3];
    const float* Wm    = (const float*)d_in[4];
    const float* bm    = (const float*)d_in[5];
    const float* gamma = (const float*)d_in[6];
    const float* beta  = (const float*)d_in[7];
    const float* Wr    = (const float*)d_in[8];
    const float* br    = (const float*)d_in[9];
    float* out = (float*)d_out;

    k_fill_xw<<<FILL_BLOCKS + NODE_WARP_BLOCKS, 256>>>(hidx, x, Wc, Wr, br);
    k_gather_edge<<<NODE_WARP_BLOCKS, 256>>>();
    k_gather_mlp<<<GM_BLOCKS, 256>>>(Wm, bm, bc, gamma, beta);
    k_final<<<FINAL_BLOCKS, 256>>>(out);
}

// round 8
// speedup vs baseline: 1.0979x; 1.0979x over previous
#include <cuda_runtime.h>
#include <cuda_bf16.h>
#include <stdint.h>

#define NN  100000
#define PP  3200000
#define IN_F  19
#define OUT_F 64
#define CAP   128
#define EPS   1e-5f
#define SLOPE 0.01f
#define FULL 0xffffffffu

#define FILL_BLOCKS 3125                 // PP / 4 / 256
#define NODE_WARP_BLOCKS 12500           // NN*32 / 256
#define MT 128                           // nodes per MLP tile
#define MLP_BLOCKS ((NN + MT - 1) / MT)  // 782
#define SO_STRIDE 132                    // padded row stride (floats)
#define FINAL_BLOCKS ((NN * OUT_F / 4 + 255) / 256)   // 6250

// ---------------- device scratch (zero-initialized at module load; restored every call) ----------------
__device__ __align__(256) float g_xw[NN * OUT_F];     // x@W_conv, then reused for conv-out o
__device__ __align__(256) float g_edge[NN * OUT_F];   // per-hyperedge features
__device__ __align__(256) float g_h[NN * OUT_F];      // pre-BN MLP output
__device__ __align__(256) float g_res[NN * OUT_F];    // residual x @ W_res + b_res
__device__ int   g_Bcnt[NN];             // hyperedge sizes   (re-zeroed in k_final)
__device__ int   g_Dcnt[NN];             // node degrees      (re-zeroed in k_final)
__device__ int   g_Elist[NN * CAP];      // node ids bucketed by edge
__device__ int   g_Nlist[NN * CAP];      // edge ids bucketed by node
__device__ __align__(16) float g_stats[4 * OUT_F];  // sum | sumsq | scale | shift (sums re-zeroed)
__device__ int   g_arrive;               // arrival counter (reset each call)

// ---------------- fused: bucket fill (blocks [0,FILL_BLOCKS)) + xw & residual GEMMs (rest) ----------------
__global__ void k_fill_xw(const void* __restrict__ idx,
                          const float* __restrict__ x, const float* __restrict__ Wc,
                          const float* __restrict__ Wr, const float* __restrict__ br) {
    __shared__ float sWc[IN_F * OUT_F];
    __shared__ float sWr[IN_F * OUT_F];
    __shared__ int s64;

    if (blockIdx.x < FILL_BLOCKS) {
        // per-block index dtype probe: int64 values < 2^32 => odd 32-bit words all zero
        if (threadIdx.x == 0) {
            const int* w = (const int*)idx;
            int is64 = 1;
            for (int j = 1; j < 64; j += 2)
                if (w[j] != 0) { is64 = 0; break; }
            s64 = is64;
        }
        __syncthreads();

        long long t4 = ((long long)blockIdx.x * blockDim.x + threadIdx.x);
        int n4[4], e4[4];
        if (s64) {
            const longlong2* b = (const longlong2*)idx;
            longlong2 a0 = b[t4 * 2], a1 = b[t4 * 2 + 1];
            longlong2 c0 = b[(PP / 2) + t4 * 2], c1 = b[(PP / 2) + t4 * 2 + 1];
            n4[0] = (int)a0.x; n4[1] = (int)a0.y; n4[2] = (int)a1.x; n4[3] = (int)a1.y;
            e4[0] = (int)c0.x; e4[1] = (int)c0.y; e4[2] = (int)c1.x; e4[3] = (int)c1.y;
        } else {
            const int4* b = (const int4*)idx;
            int4 a = b[t4];
            int4 c = b[(PP / 4) + t4];
            n4[0] = a.x; n4[1] = a.y; n4[2] = a.z; n4[3] = a.w;
            e4[0] = c.x; e4[1] = c.y; e4[2] = c.z; e4[3] = c.w;
        }
#pragma unroll
        for (int q = 0; q < 4; q++) {
            int n = n4[q], e = e4[q];
            if ((unsigned)n >= NN || (unsigned)e >= NN) continue;
            int pe = atomicAdd(&g_Bcnt[e], 1);
            if (pe < CAP) g_Elist[e * CAP + pe] = n;
            int pn = atomicAdd(&g_Dcnt[n], 1);
            if (pn < CAP) g_Nlist[n * CAP + pn] = e;
        }
    } else {
        // ---- xw = x @ W_conv and res = x @ W_res + b_res, one warp per node ----
        for (int i = threadIdx.x; i < IN_F * OUT_F; i += blockDim.x) {
            sWc[i] = Wc[i];
            sWr[i] = Wr[i];
        }
        __syncthreads();

        int warp = (int)(((long long)(blockIdx.x - FILL_BLOCKS) * blockDim.x + threadIdx.x) >> 5);
        int lane = threadIdx.x & 31;
        if (warp >= NN) return;

        float xv = (lane < IN_F) ? x[(int64_t)warp * IN_F + lane] : 0.f;
        float a0 = 0.f, a1 = 0.f;
        float r0 = br[lane], r1 = br[lane + 32];
#pragma unroll
        for (int k = 0; k < IN_F; k++) {
            float xk = __shfl_sync(FULL, xv, k);
            a0 = fmaf(xk, sWc[k * OUT_F + lane],      a0);
            a1 = fmaf(xk, sWc[k * OUT_F + lane + 32], a1);
            r0 = fmaf(xk, sWr[k * OUT_F + lane],      r0);
            r1 = fmaf(xk, sWr[k * OUT_F + lane + 32], r1);
        }
        g_xw[warp * OUT_F + lane]       = a0;
        g_xw[warp * OUT_F + lane + 32]  = a1;
        g_res[warp * OUT_F + lane]      = r0;
        g_res[warp * OUT_F + lane + 32] = r1;
    }
}

// ---------------- pass 1: gather node rows -> edge rows (B^-1 fused) ----------------
__global__ void k_gather_edge() {
    int warp = (blockIdx.x * blockDim.x + threadIdx.x) >> 5;
    int lane = threadIdx.x & 31;
    if (warp >= NN) return;

    int cnt = min(g_Bcnt[warp], CAP);
    const int* lst = &g_Elist[warp * CAP];
    int hw = lane >> 4, sl = lane & 15;

    float4 acc = make_float4(0.f, 0.f, 0.f, 0.f);
    for (int jb = 0; jb < cnt; jb += 32) {
        int m = (jb + lane < cnt) ? lst[jb + lane] : 0;
        int lim = min(32, cnt - jb);
        int even = lim & ~1;
#pragma unroll 4
        for (int k = 0; k < even; k += 2) {
            int n = __shfl_sync(FULL, m, k + hw);
            float4 v = *reinterpret_cast<const float4*>(&g_xw[n * OUT_F + sl * 4]);
            acc.x += v.x; acc.y += v.y; acc.z += v.z; acc.w += v.w;
        }
        if (lim & 1) {
            int n = __shfl_sync(FULL, m, even);
            if (hw == 0) {
                float4 v = *reinterpret_cast<const float4*>(&g_xw[n * OUT_F + sl * 4]);
                acc.x += v.x; acc.y += v.y; acc.z += v.z; acc.w += v.w;
            }
        }
    }
    acc.x += __shfl_xor_sync(FULL, acc.x, 16);
    acc.y += __shfl_xor_sync(FULL, acc.y, 16);
    acc.z += __shfl_xor_sync(FULL, acc.z, 16);
    acc.w += __shfl_xor_sync(FULL, acc.w, 16);

    float s = (cnt > 0) ? (1.f / (float)cnt) : 0.f;
    acc.x *= s; acc.y *= s; acc.z *= s; acc.w *= s;
    if (hw == 0)
        *reinterpret_cast<float4*>(&g_edge[warp * OUT_F + sl * 4]) = acc;
}

// ---------------- pass 2: gather edge rows -> conv out o (D^-1 + bc fused), write to g_xw ----------------
__global__ void k_gather_node(const float* __restrict__ bc) {
    int warp = (blockIdx.x * blockDim.x + threadIdx.x) >> 5;
    int lane = threadIdx.x & 31;
    if (warp >= NN) return;

    int cnt = min(g_Dcnt[warp], CAP);
    const int* lst = &g_Nlist[warp * CAP];
    int hw = lane >> 4, sl = lane & 15;

    float4 acc = make_float4(0.f, 0.f, 0.f, 0.f);
    for (int jb = 0; jb < cnt; jb += 32) {
        int m = (jb + lane < cnt) ? lst[jb + lane] : 0;
        int lim = min(32, cnt - jb);
        int even = lim & ~1;
#pragma unroll 4
        for (int k = 0; k < even; k += 2) {
            int e = __shfl_sync(FULL, m, k + hw);
            float4 v = *reinterpret_cast<const float4*>(&g_edge[e * OUT_F + sl * 4]);
            acc.x += v.x; acc.y += v.y; acc.z += v.z; acc.w += v.w;
        }
        if (lim & 1) {
            int e = __shfl_sync(FULL, m, even);
            if (hw == 0) {
                float4 v = *reinterpret_cast<const float4*>(&g_edge[e * OUT_F + sl * 4]);
                acc.x += v.x; acc.y += v.y; acc.z += v.z; acc.w += v.w;
            }
        }
    }
    acc.x += __shfl_xor_sync(FULL, acc.x, 16);
    acc.y += __shfl_xor_sync(FULL, acc.y, 16);
    acc.z += __shfl_xor_sync(FULL, acc.z, 16);
    acc.w += __shfl_xor_sync(FULL, acc.w, 16);

    float dinv = (cnt > 0) ? (1.f / (float)cnt) : 0.f;
    if (hw == 0) {
        float4 bc4 = *reinterpret_cast<const float4*>(&bc[sl * 4]);
        acc.x = acc.x * dinv + bc4.x;
        acc.y = acc.y * dinv + bc4.y;
        acc.z = acc.z * dinv + bc4.z;
        acc.w = acc.w * dinv + bc4.w;
        *reinterpret_cast<float4*>(&g_xw[warp * OUT_F + sl * 4]) = acc;
    }
}

// ---------------- tiled MLP GEMM: h = o @ Wm + bm, + BN stats (last block finalizes) ----------------
__global__ __launch_bounds__(256, 4) void k_mlp(
        const float* __restrict__ Wm, const float* __restrict__ bm,
        const float* __restrict__ gamma, const float* __restrict__ beta) {
    __shared__ float sO[OUT_F * SO_STRIDE];   // [k][node], padded (33.8 KB)
    __shared__ float sW[OUT_F * OUT_F];       // [k][f] (16 KB)
    __shared__ float sred[2 * OUT_F];
    __shared__ int sLast;

    int tid = threadIdx.x;
    for (int i = tid; i < OUT_F * OUT_F; i += 256) sW[i] = Wm[i];
    if (tid < 2 * OUT_F) sred[tid] = 0.f;

    int base = blockIdx.x * MT;
    // load o tile transposed: idx -> (node, f4)
    for (int idx = tid; idx < MT * (OUT_F / 4); idx += 256) {
        int node = idx >> 4, f4 = idx & 15;
        float4 v = make_float4(0.f, 0.f, 0.f, 0.f);
        if (base + node < NN)
            v = *reinterpret_cast<const float4*>(&g_xw[(base + node) * OUT_F + f4 * 4]);
        sO[(f4 * 4 + 0) * SO_STRIDE + node] = v.x;
        sO[(f4 * 4 + 1) * SO_STRIDE + node] = v.y;
        sO[(f4 * 4 + 2) * SO_STRIDE + node] = v.z;
        sO[(f4 * 4 + 3) * SO_STRIDE + node] = v.w;
    }
    __syncthreads();

    int ngrp = tid & 31, fgrp = tid >> 5;
    float bmv[8];
#pragma unroll
    for (int j = 0; j < 8; j++) bmv[j] = bm[fgrp * 8 + j];

    float acc[4][8];
#pragma unroll
    for (int i = 0; i < 4; i++)
#pragma unroll
        for (int j = 0; j < 8; j++) acc[i][j] = bmv[j];

#pragma unroll 8
    for (int k = 0; k < OUT_F; k++) {
        float4 o4 = *reinterpret_cast<const float4*>(&sO[k * SO_STRIDE + ngrp * 4]);
        float4 w0 = *reinterpret_cast<const float4*>(&sW[k * OUT_F + fgrp * 8]);
        float4 w1 = *reinterpret_cast<const float4*>(&sW[k * OUT_F + fgrp * 8 + 4]);
        float o[4] = {o4.x, o4.y, o4.z, o4.w};
        float w[8] = {w0.x, w0.y, w0.z, w0.w, w1.x, w1.y, w1.z, w1.w};
#pragma unroll
        for (int i = 0; i < 4; i++)
#pragma unroll
            for (int j = 0; j < 8; j++)
                acc[i][j] = fmaf(o[i], w[j], acc[i][j]);
    }

    // store h + BN partials (valid nodes only)
    float s[8], q[8];
#pragma unroll
    for (int j = 0; j < 8; j++) { s[j] = 0.f; q[j] = 0.f; }
#pragma unroll
    for (int i = 0; i < 4; i++) {
        int node = base + ngrp * 4 + i;
        if (node < NN) {
            float4 h0 = make_float4(acc[i][0], acc[i][1], acc[i][2], acc[i][3]);
            float4 h1 = make_float4(acc[i][4], acc[i][5], acc[i][6], acc[i][7]);
            *reinterpret_cast<float4*>(&g_h[node * OUT_F + fgrp * 8])     = h0;
            *reinterpret_cast<float4*>(&g_h[node * OUT_F + fgrp * 8 + 4]) = h1;
#pragma unroll
            for (int j = 0; j < 8; j++) {
                s[j] += acc[i][j];
                q[j] += acc[i][j] * acc[i][j];
            }
        }
    }
#pragma unroll
    for (int off = 16; off > 0; off >>= 1) {
#pragma unroll
        for (int j = 0; j < 8; j++) {
            s[j] += __shfl_xor_sync(FULL, s[j], off);
            q[j] += __shfl_xor_sync(FULL, q[j], off);
        }
    }
    if (ngrp == 0) {
#pragma unroll
        for (int j = 0; j < 8; j++) {
            atomicAdd(&sred[fgrp * 8 + j],         s[j]);
            atomicAdd(&sred[OUT_F + fgrp * 8 + j], q[j]);
        }
    }
    __syncthreads();
    if (tid < 2 * OUT_F) atomicAdd(&g_stats[tid], sred[tid]);

    // last block finalizes BN scale/shift and resets sums
    __threadfence();
    if (tid == 0) {
        int prev = atomicAdd(&g_arrive, 1);
        sLast = (prev == gridDim.x - 1);
    }
    __syncthreads();
    if (sLast) {
        if (tid < OUT_F) {
            int f = tid;
            float mean = g_stats[f] / (float)NN;
            float var  = g_stats[OUT_F + f] / (float)NN - mean * mean;
            float inv  = rsqrtf(var + EPS);
            float sc   = gamma[f] * inv;
            g_stats[2 * OUT_F + f] = sc;
            g_stats[3 * OUT_F + f] = beta[f] - sc * mean;
            g_stats[f] = 0.f;
            g_stats[OUT_F + f] = 0.f;
        }
        if (tid == 0) g_arrive = 0;
    }
}

// ---------------- final: BN apply + LeakyReLU + residual + LeakyReLU (pure elementwise) ----------------
__global__ void k_final(float* __restrict__ out) {
    int i = blockIdx.x * blockDim.x + threadIdx.x;
    if (i < NN) { g_Bcnt[i] = 0; g_Dcnt[i] = 0; }   // restore zeros for next call
    if (i >= NN * (OUT_F / 4)) return;

    int f4 = i & 15;           // feature group (x4)
    float4 h  = reinterpret_cast<const float4*>(g_h)[i];
    float4 r  = reinterpret_cast<const float4*>(g_res)[i];
    float4 sc = *reinterpret_cast<const float4*>(&g_stats[2 * OUT_F + f4 * 4]);
    float4 sh = *reinterpret_cast<const float4*>(&g_stats[3 * OUT_F + f4 * 4]);

    float y[4];
    y[0] = h.x * sc.x + sh.x; y[1] = h.y * sc.y + sh.y;
    y[2] = h.z * sc.z + sh.z; y[3] = h.w * sc.w + sh.w;
    float rr[4] = {r.x, r.y, r.z, r.w};
#pragma unroll
    for (int j = 0; j < 4; j++) {
        float v = y[j];
        v = (v >= 0.f) ? v : SLOPE * v;
        v += rr[j];
        y[j] = (v >= 0.f) ? v : SLOPE * v;
    }
    reinterpret_cast<float4*>(out)[i] = make_float4(y[0], y[1], y[2], y[3]);
}

// ---------------- launcher ----------------
extern "C" void kernel_launch(void* const* d_in, const int* in_sizes, int n_in,
                              void* d_out, int out_size) {
    const float* x     = (const float*)d_in[0];
    const void*  hidx  = d_in[1];
    const float* Wc    = (const float*)d_in[2];
    const float* bc    = (const float*)d_in[3];
    const float* Wm    = (const float*)d_in[4];
    const float* bm    = (const float*)d_in[5];
    const float* gamma = (const float*)d_in[6];
    const float* beta  = (const float*)d_in[7];
    const float* Wr    = (const float*)d_in[8];
    const float* br    = (const float*)d_in[9];
    float* out = (float*)d_out;

    k_fill_xw<<<FILL_BLOCKS + NODE_WARP_BLOCKS, 256>>>(hidx, x, Wc, Wr, br);
    k_gather_edge<<<NODE_WARP_BLOCKS, 256>>>();
    k_gather_node<<<NODE_WARP_BLOCKS, 256>>>(bc);
    k_mlp<<<MLP_BLOCKS, 256>>>(Wm, bm, gamma, beta);
    k_final<<<FINAL_BLOCKS, 256>>>(out);
}

// round 9
// speedup vs baseline: 1.1737x; 1.0690x over previous
#include <cuda_runtime.h>
#include <cuda_bf16.h>
#include <stdint.h>

#define NN  100000
#define PP  3200000
#define IN_F  19
#define OUT_F 64
#define CAP   128
#define EPS   1e-5f
#define SLOPE 0.01f
#define FULL 0xffffffffu

#define FILL_BLOCKS 3125                 // PP / 4 / 256
#define NODE_WARP_BLOCKS 12500           // NN*32 / 256
#define BN_BLOCKS 256
#define FINAL_BLOCKS ((NN * OUT_F / 4 + 255) / 256)   // 6250

// ---------------- device scratch (zero-initialized at module load; restored every call) ----------------
__device__ __align__(256) float g_xw[NN * OUT_F];     // z = x @ (Wc@Wm)
__device__ __align__(256) float g_edge[NN * OUT_F];   // per-hyperedge transformed features
__device__ __align__(256) float g_h[NN * OUT_F];      // pre-BN MLP output (direct from gather)
__device__ __align__(256) float g_res[NN * OUT_F];    // residual x @ W_res + b_res
__device__ int   g_Bcnt[NN];             // hyperedge sizes   (re-zeroed in k_final)
__device__ int   g_Dcnt[NN];             // node degrees      (re-zeroed in k_final)
__device__ int   g_Elist[NN * CAP];      // node ids bucketed by edge
__device__ int   g_Nlist[NN * CAP];      // edge ids bucketed by node
__device__ __align__(16) float g_stats[4 * OUT_F];  // sum | sumsq | scale | shift (sums re-zeroed)
__device__ float g_Wcm[IN_F * OUT_F];    // folded weight Wc @ Wm
__device__ __align__(16) float g_bconst[OUT_F];     // bc @ Wm + bm
__device__ int   g_arrive;               // arrival counter (reset each call)

// ---------------- tiny: fold weights Wcm = Wc@Wm, bconst = bc@Wm + bm ----------------
__global__ void k_wcm(const float* __restrict__ Wc, const float* __restrict__ bc,
                      const float* __restrict__ Wm, const float* __restrict__ bm) {
    __shared__ float sWm[OUT_F * OUT_F];
    int tid = threadIdx.x;
    for (int i = tid; i < OUT_F * OUT_F; i += 256) sWm[i] = Wm[i];
    __syncthreads();

    int j = tid & 63, krow = tid >> 6;
    for (int k = krow; k < IN_F; k += 4) {
        float acc = 0.f;
#pragma unroll 8
        for (int m = 0; m < OUT_F; m++)
            acc = fmaf(Wc[k * OUT_F + m], sWm[m * OUT_F + j], acc);
        g_Wcm[k * OUT_F + j] = acc;
    }
    if (tid < OUT_F) {
        float acc = bm[tid];
#pragma unroll 8
        for (int m = 0; m < OUT_F; m++)
            acc = fmaf(bc[m], sWm[m * OUT_F + tid], acc);
        g_bconst[tid] = acc;
    }
}

// ---------------- fused: bucket fill (blocks [0,FILL_BLOCKS)) + z & residual GEMMs (rest) ----------------
__global__ void k_fill_xw(const void* __restrict__ idx,
                          const float* __restrict__ x,
                          const float* __restrict__ Wr, const float* __restrict__ br) {
    __shared__ float sWc[IN_F * OUT_F];
    __shared__ float sWr[IN_F * OUT_F];
    __shared__ int s64;

    if (blockIdx.x < FILL_BLOCKS) {
        // per-block index dtype probe: int64 values < 2^32 => odd 32-bit words all zero
        if (threadIdx.x == 0) {
            const int* w = (const int*)idx;
            int is64 = 1;
            for (int j = 1; j < 64; j += 2)
                if (w[j] != 0) { is64 = 0; break; }
            s64 = is64;
        }
        __syncthreads();

        long long t4 = ((long long)blockIdx.x * blockDim.x + threadIdx.x);
        int n4[4], e4[4];
        if (s64) {
            const longlong2* b = (const longlong2*)idx;
            longlong2 a0 = b[t4 * 2], a1 = b[t4 * 2 + 1];
            longlong2 c0 = b[(PP / 2) + t4 * 2], c1 = b[(PP / 2) + t4 * 2 + 1];
            n4[0] = (int)a0.x; n4[1] = (int)a0.y; n4[2] = (int)a1.x; n4[3] = (int)a1.y;
            e4[0] = (int)c0.x; e4[1] = (int)c0.y; e4[2] = (int)c1.x; e4[3] = (int)c1.y;
        } else {
            const int4* b = (const int4*)idx;
            int4 a = b[t4];
            int4 c = b[(PP / 4) + t4];
            n4[0] = a.x; n4[1] = a.y; n4[2] = a.z; n4[3] = a.w;
            e4[0] = c.x; e4[1] = c.y; e4[2] = c.z; e4[3] = c.w;
        }
#pragma unroll
        for (int q = 0; q < 4; q++) {
            int n = n4[q], e = e4[q];
            if ((unsigned)n >= NN || (unsigned)e >= NN) continue;
            int pe = atomicAdd(&g_Bcnt[e], 1);
            if (pe < CAP) g_Elist[e * CAP + pe] = n;
            int pn = atomicAdd(&g_Dcnt[n], 1);
            if (pn < CAP) g_Nlist[n * CAP + pn] = e;
        }
    } else {
        // ---- z = x @ Wcm and res = x @ W_res + b_res, one warp per node ----
        for (int i = threadIdx.x; i < IN_F * OUT_F; i += blockDim.x) {
            sWc[i] = g_Wcm[i];
            sWr[i] = Wr[i];
        }
        __syncthreads();

        int warp = (int)(((long long)(blockIdx.x - FILL_BLOCKS) * blockDim.x + threadIdx.x) >> 5);
        int lane = threadIdx.x & 31;
        if (warp >= NN) return;

        float xv = (lane < IN_F) ? x[(int64_t)warp * IN_F + lane] : 0.f;
        float a0 = 0.f, a1 = 0.f;
        float r0 = br[lane], r1 = br[lane + 32];
#pragma unroll
        for (int k = 0; k < IN_F; k++) {
            float xk = __shfl_sync(FULL, xv, k);
            a0 = fmaf(xk, sWc[k * OUT_F + lane],      a0);
            a1 = fmaf(xk, sWc[k * OUT_F + lane + 32], a1);
            r0 = fmaf(xk, sWr[k * OUT_F + lane],      r0);
            r1 = fmaf(xk, sWr[k * OUT_F + lane + 32], r1);
        }
        g_xw[warp * OUT_F + lane]       = a0;
        g_xw[warp * OUT_F + lane + 32]  = a1;
        g_res[warp * OUT_F + lane]      = r0;
        g_res[warp * OUT_F + lane + 32] = r1;
    }
}

// ---------------- pass 1: gather node rows -> edge rows (B^-1 fused) ----------------
__global__ void k_gather_edge() {
    int warp = (blockIdx.x * blockDim.x + threadIdx.x) >> 5;
    int lane = threadIdx.x & 31;
    if (warp >= NN) return;

    int cnt = min(g_Bcnt[warp], CAP);
    const int* lst = &g_Elist[warp * CAP];
    int hw = lane >> 4, sl = lane & 15;

    float4 acc = make_float4(0.f, 0.f, 0.f, 0.f);
    for (int jb = 0; jb < cnt; jb += 32) {
        int m = (jb + lane < cnt) ? lst[jb + lane] : 0;
        int lim = min(32, cnt - jb);
        int even = lim & ~1;
#pragma unroll 4
        for (int k = 0; k < even; k += 2) {
            int n = __shfl_sync(FULL, m, k + hw);
            float4 v = *reinterpret_cast<const float4*>(&g_xw[n * OUT_F + sl * 4]);
            acc.x += v.x; acc.y += v.y; acc.z += v.z; acc.w += v.w;
        }
        if (lim & 1) {
            int n = __shfl_sync(FULL, m, even);
            if (hw == 0) {
                float4 v = *reinterpret_cast<const float4*>(&g_xw[n * OUT_F + sl * 4]);
                acc.x += v.x; acc.y += v.y; acc.z += v.z; acc.w += v.w;
            }
        }
    }
    acc.x += __shfl_xor_sync(FULL, acc.x, 16);
    acc.y += __shfl_xor_sync(FULL, acc.y, 16);
    acc.z += __shfl_xor_sync(FULL, acc.z, 16);
    acc.w += __shfl_xor_sync(FULL, acc.w, 16);

    float s = (cnt > 0) ? (1.f / (float)cnt) : 0.f;
    acc.x *= s; acc.y *= s; acc.z *= s; acc.w *= s;
    if (hw == 0)
        *reinterpret_cast<float4*>(&g_edge[warp * OUT_F + sl * 4]) = acc;
}

// ---------------- pass 2: gather edge rows -> h = D^-1*acc + bconst, write g_h ----------------
__global__ void k_gather_node() {
    int warp = (blockIdx.x * blockDim.x + threadIdx.x) >> 5;
    int lane = threadIdx.x & 31;
    if (warp >= NN) return;

    int cnt = min(g_Dcnt[warp], CAP);
    const int* lst = &g_Nlist[warp * CAP];
    int hw = lane >> 4, sl = lane & 15;

    float4 acc = make_float4(0.f, 0.f, 0.f, 0.f);
    for (int jb = 0; jb < cnt; jb += 32) {
        int m = (jb + lane < cnt) ? lst[jb + lane] : 0;
        int lim = min(32, cnt - jb);
        int even = lim & ~1;
#pragma unroll 4
        for (int k = 0; k < even; k += 2) {
            int e = __shfl_sync(FULL, m, k + hw);
            float4 v = *reinterpret_cast<const float4*>(&g_edge[e * OUT_F + sl * 4]);
            acc.x += v.x; acc.y += v.y; acc.z += v.z; acc.w += v.w;
        }
        if (lim & 1) {
            int e = __shfl_sync(FULL, m, even);
            if (hw == 0) {
                float4 v = *reinterpret_cast<const float4*>(&g_edge[e * OUT_F + sl * 4]);
                acc.x += v.x; acc.y += v.y; acc.z += v.z; acc.w += v.w;
            }
        }
    }
    acc.x += __shfl_xor_sync(FULL, acc.x, 16);
    acc.y += __shfl_xor_sync(FULL, acc.y, 16);
    acc.z += __shfl_xor_sync(FULL, acc.z, 16);
    acc.w += __shfl_xor_sync(FULL, acc.w, 16);

    float dinv = (cnt > 0) ? (1.f / (float)cnt) : 0.f;
    if (hw == 0) {
        float4 b4 = *reinterpret_cast<const float4*>(&g_bconst[sl * 4]);
        acc.x = acc.x * dinv + b4.x;
        acc.y = acc.y * dinv + b4.y;
        acc.z = acc.z * dinv + b4.z;
        acc.w = acc.w * dinv + b4.w;
        *reinterpret_cast<float4*>(&g_h[warp * OUT_F + sl * 4]) = acc;
    }
}

// ---------------- BN stats: reduce g_h -> mean/var -> scale/shift (last block finalizes) ----------------
__global__ void k_bnstats(const float* __restrict__ gamma, const float* __restrict__ beta) {
    __shared__ float sred[2 * OUT_F];
    __shared__ int sLast;
    int tid = threadIdx.x;
    if (tid < 2 * OUT_F) sred[tid] = 0.f;
    __syncthreads();

    const int TOT = NN * (OUT_F / 4);            // 1.6M float4s
    int f4 = tid & 15;                           // constant per thread (stride % 16 == 0)
    float s[4] = {0.f, 0.f, 0.f, 0.f};
    float q[4] = {0.f, 0.f, 0.f, 0.f};
    for (int i = blockIdx.x * 256 + tid; i < TOT; i += 256 * BN_BLOCKS) {
        float4 h = reinterpret_cast<const float4*>(g_h)[i];
        s[0] += h.x; q[0] += h.x * h.x;
        s[1] += h.y; q[1] += h.y * h.y;
        s[2] += h.z; q[2] += h.z * h.z;
        s[3] += h.w; q[3] += h.w * h.w;
    }
#pragma unroll
    for (int j = 0; j < 4; j++) {
        atomicAdd(&sred[f4 * 4 + j],         s[j]);
        atomicAdd(&sred[OUT_F + f4 * 4 + j], q[j]);
    }
    __syncthreads();
    if (tid < 2 * OUT_F) atomicAdd(&g_stats[tid], sred[tid]);

    __threadfence();
    if (tid == 0) {
        int prev = atomicAdd(&g_arrive, 1);
        sLast = (prev == gridDim.x - 1);
    }
    __syncthreads();
    if (sLast) {
        if (tid < OUT_F) {
            int f = tid;
            float mean = g_stats[f] / (float)NN;
            float var  = g_stats[OUT_F + f] / (float)NN - mean * mean;
            float inv  = rsqrtf(var + EPS);
            float sc   = gamma[f] * inv;
            g_stats[2 * OUT_F + f] = sc;
            g_stats[3 * OUT_F + f] = beta[f] - sc * mean;
            g_stats[f] = 0.f;
            g_stats[OUT_F + f] = 0.f;
        }
        if (tid == 0) g_arrive = 0;
    }
}

// ---------------- final: BN apply + LeakyReLU + residual + LeakyReLU (pure elementwise) ----------------
__global__ void k_final(float* __restrict__ out) {
    int i = blockIdx.x * blockDim.x + threadIdx.x;
    if (i < NN) { g_Bcnt[i] = 0; g_Dcnt[i] = 0; }   // restore zeros for next call
    if (i >= NN * (OUT_F / 4)) return;

    int f4 = i & 15;
    float4 h  = reinterpret_cast<const float4*>(g_h)[i];
    float4 r  = reinterpret_cast<const float4*>(g_res)[i];
    float4 sc = *reinterpret_cast<const float4*>(&g_stats[2 * OUT_F + f4 * 4]);
    float4 sh = *reinterpret_cast<const float4*>(&g_stats[3 * OUT_F + f4 * 4]);

    float y[4];
    y[0] = h.x * sc.x + sh.x; y[1] = h.y * sc.y + sh.y;
    y[2] = h.z * sc.z + sh.z; y[3] = h.w * sc.w + sh.w;
    float rr[4] = {r.x, r.y, r.z, r.w};
#pragma unroll
    for (int j = 0; j < 4; j++) {
        float v = y[j];
        v = (v >= 0.f) ? v : SLOPE * v;
        v += rr[j];
        y[j] = (v >= 0.f) ? v : SLOPE * v;
    }
    reinterpret_cast<float4*>(out)[i] = make_float4(y[0], y[1], y[2], y[3]);
}

// ---------------- launcher ----------------
extern "C" void kernel_launch(void* const* d_in, const int* in_sizes, int n_in,
                              void* d_out, int out_size) {
    const float* x     = (const float*)d_in[0];
    const void*  hidx  = d_in[1];
    const float* Wc    = (const float*)d_in[2];
    const float* bc    = (const float*)d_in[3];
    const float* Wm    = (const float*)d_in[4];
    const float* bm    = (const float*)d_in[5];
    const float* gamma = (const float*)d_in[6];
    const float* beta  = (const float*)d_in[7];
    const float* Wr    = (const float*)d_in[8];
    const float* br    = (const float*)d_in[9];
    float* out = (float*)d_out;

    k_wcm<<<1, 256>>>(Wc, bc, Wm, bm);
    k_fill_xw<<<FILL_BLOCKS + NODE_WARP_BLOCKS, 256>>>(hidx, x, Wr, br);
    k_gather_edge<<<NODE_WARP_BLOCKS, 256>>>();
    k_gather_node<<<NODE_WARP_BLOCKS, 256>>>();
    k_bnstats<<<BN_BLOCKS, 256>>>(gamma, beta);
    k_final<<<FINAL_BLOCKS, 256>>>(out);
}